// round 13
// baseline (speedup 1.0000x reference)
#include <cuda_runtime.h>
#include <cuda_bf16.h>
#include <stdint.h>
#include <math.h>
#include <float.h>

#define NB   128
#define N0C  512
#define EPG  4096
#define ETOT (NB*EPG)
#define H    128
#define NMAX (NB*N0C)
#define WSTR 136   // padded bf16 row stride (272B = 17 x 16B granules)

// ---------------- scratch ---------------------------------------------------
__device__ float d_hA[NMAX*H];   // layer input h
__device__ float d_hB[NMAX*H];   // m = h @ W
__device__ float d_hC[NMAX*H];   // pre-BN h
__device__ int   d_ls[ETOT];
__device__ int   d_ld[ETOT];
__device__ float d_w[ETOT];
__device__ unsigned short d_csrc[ETOT];
__device__ float d_cen[ETOT];
__device__ int   d_rowptr[NB*513];
__device__ float d_dinv[NMAX];
__device__ float d_bnsum[5][H];
__device__ float d_bnsq[5][H];
__device__ float d_reads[NB*2*H];
__device__ float d_g1[NB*H];
__device__ float d_g2[NB*(H/2)];
// W^T bf16 hi/lo images, [n][k] layout with WSTR stride, per layer
__device__ __align__(16) __nv_bfloat16 d_Whi[5*128*WSTR];
__device__ __align__(16) __nv_bfloat16 d_Wlo[5*128*WSTR];

// ---------------- helpers -----------------------------------------------------
__device__ __forceinline__ unsigned int f2u(float f) {
    unsigned int u = __float_as_uint(f);
    return (u & 0x80000000u) ? ~u : (u | 0x80000000u);
}
__device__ __forceinline__ uint32_t smem_u32(const void* p) {
    uint32_t a;
    asm("{ .reg .u64 t; cvta.to.shared.u64 t, %1; cvt.u32.u64 %0, t; }"
        : "=r"(a) : "l"(p));
    return a;
}

// ---------------- W prep: decompose convW into W^T bf16 hi/lo ----------------
__global__ void k_wprep(const float* __restrict__ convW) {
    int l = blockIdx.x, t = threadIdx.x;   // 256 threads
    const float* W = convW + l*16384;
    __nv_bfloat16* hi = &d_Whi[l*128*WSTR];
    __nv_bfloat16* lo = &d_Wlo[l*128*WSTR];
    for (int i = t; i < 16384; i += 256) {
        int kk = i >> 7, nn = i & 127;         // W[kk][nn]
        float w = W[i];
        __nv_bfloat16 h = __float2bfloat16(w);
        __nv_bfloat16 r = __float2bfloat16(w - __bfloat162float(h));
        hi[nn*WSTR + kk] = h;
        lo[nn*WSTR + kk] = r;
    }
}

// ------- tensor-core GEMM via mma.sync bf16x3: hB = A @ W --------------------
// block: 256 thr (8 warps), tile = 128 rows x 128 cols; warp w -> rows w*16..+16
#define SA_HI 0
#define SA_LO 34816
#define SW_HI 69632
#define SW_LO 104448
#define SM_TOT 139264

__global__ void __launch_bounds__(256, 1) k_gemm_tc(const float* __restrict__ A, int layer) {
    extern __shared__ __align__(16) char smem[];
    uint32_t sb = smem_u32(smem);
    int t = threadIdx.x, wid = t >> 5, lane = t & 31;
    int row0 = blockIdx.x * 128;

    // copy W images (hi/lo), 128*WSTR bf16 = 2176 uint4 each
    {
        const uint4* wh = (const uint4*)&d_Whi[layer*128*WSTR];
        const uint4* wl = (const uint4*)&d_Wlo[layer*128*WSTR];
        uint4* sh = (uint4*)(smem + SW_HI);
        uint4* sl = (uint4*)(smem + SW_LO);
        for (int i = t; i < 2176; i += 256) { sh[i] = wh[i]; sl[i] = wl[i]; }
    }
    // load + decompose A tile [128 x 128] -> Ahi/Alo [row][k], stride WSTR
    {
        __nv_bfloat16* ah = (__nv_bfloat16*)(smem + SA_HI);
        __nv_bfloat16* al = (__nv_bfloat16*)(smem + SA_LO);
        for (int i = t; i < 4096; i += 256) {
            int row = i >> 5, k4 = (i & 31) * 4;
            float4 a = *(const float4*)(A + (size_t)(row0 + row)*128 + k4);
            __nv_bfloat16 h0 = __float2bfloat16(a.x), h1 = __float2bfloat16(a.y);
            __nv_bfloat16 h2 = __float2bfloat16(a.z), h3 = __float2bfloat16(a.w);
            __nv_bfloat16 l0 = __float2bfloat16(a.x - __bfloat162float(h0));
            __nv_bfloat16 l1 = __float2bfloat16(a.y - __bfloat162float(h1));
            __nv_bfloat16 l2 = __float2bfloat16(a.z - __bfloat162float(h2));
            __nv_bfloat16 l3 = __float2bfloat16(a.w - __bfloat162float(h3));
            __nv_bfloat162 hp0 = __halves2bfloat162(h0, h1);
            __nv_bfloat162 hp1 = __halves2bfloat162(h2, h3);
            __nv_bfloat162 lp0 = __halves2bfloat162(l0, l1);
            __nv_bfloat162 lp1 = __halves2bfloat162(l2, l3);
            *(uint2*)&ah[row*WSTR + k4] = make_uint2(*(unsigned*)&hp0, *(unsigned*)&hp1);
            *(uint2*)&al[row*WSTR + k4] = make_uint2(*(unsigned*)&lp0, *(unsigned*)&lp1);
        }
    }
    __syncthreads();

    float d[16][4];
    #pragma unroll
    for (int nt = 0; nt < 16; nt++) {
        d[nt][0] = 0.f; d[nt][1] = 0.f; d[nt][2] = 0.f; d[nt][3] = 0.f;
    }

    int warpRow = wid * 16;
    // A ldmatrix x4 address: lanes 0-15 -> rows 0-15 (k lo 8), 16-31 -> rows 0-15 (k hi 8)
    int arow = warpRow + (lane & 15);
    int akoff = (lane >> 4) * 8;
    // B ldmatrix x2 address: lanes 0-7 -> n rows (k lo), 8-15 -> n rows (k hi)
    int bnr = lane & 7;
    int bkoff = ((lane >> 3) & 1) * 8;

    #pragma unroll
    for (int ks = 0; ks < 8; ks++) {
        int k0 = ks * 16;
        uint32_t aAddrH = sb + SA_HI + (uint32_t)(arow*WSTR + k0 + akoff) * 2u;
        uint32_t aAddrL = sb + SA_LO + (uint32_t)(arow*WSTR + k0 + akoff) * 2u;
        uint32_t ah0, ah1, ah2, ah3, al0, al1, al2, al3;
        asm volatile("ldmatrix.sync.aligned.m8n8.x4.shared.b16 {%0,%1,%2,%3}, [%4];"
                     : "=r"(ah0), "=r"(ah1), "=r"(ah2), "=r"(ah3) : "r"(aAddrH));
        asm volatile("ldmatrix.sync.aligned.m8n8.x4.shared.b16 {%0,%1,%2,%3}, [%4];"
                     : "=r"(al0), "=r"(al1), "=r"(al2), "=r"(al3) : "r"(aAddrL));
        uint32_t bBaseH = sb + SW_HI + (uint32_t)(bnr*WSTR + k0 + bkoff) * 2u;
        uint32_t bBaseL = sb + SW_LO + (uint32_t)(bnr*WSTR + k0 + bkoff) * 2u;
        #pragma unroll
        for (int nt = 0; nt < 16; nt++) {
            uint32_t off = (uint32_t)(nt * 8 * WSTR) * 2u;
            uint32_t bh0, bh1, bl0, bl1;
            asm volatile("ldmatrix.sync.aligned.m8n8.x2.shared.b16 {%0,%1}, [%2];"
                         : "=r"(bh0), "=r"(bh1) : "r"(bBaseH + off));
            asm volatile("ldmatrix.sync.aligned.m8n8.x2.shared.b16 {%0,%1}, [%2];"
                         : "=r"(bl0), "=r"(bl1) : "r"(bBaseL + off));
            asm volatile("mma.sync.aligned.m16n8k16.row.col.f32.bf16.bf16.f32 "
                         "{%0,%1,%2,%3}, {%4,%5,%6,%7}, {%8,%9}, {%0,%1,%2,%3};"
                         : "+f"(d[nt][0]), "+f"(d[nt][1]), "+f"(d[nt][2]), "+f"(d[nt][3])
                         : "r"(ah0), "r"(ah1), "r"(ah2), "r"(ah3), "r"(bh0), "r"(bh1));
            asm volatile("mma.sync.aligned.m16n8k16.row.col.f32.bf16.bf16.f32 "
                         "{%0,%1,%2,%3}, {%4,%5,%6,%7}, {%8,%9}, {%0,%1,%2,%3};"
                         : "+f"(d[nt][0]), "+f"(d[nt][1]), "+f"(d[nt][2]), "+f"(d[nt][3])
                         : "r"(ah0), "r"(ah1), "r"(ah2), "r"(ah3), "r"(bl0), "r"(bl1));
            asm volatile("mma.sync.aligned.m16n8k16.row.col.f32.bf16.bf16.f32 "
                         "{%0,%1,%2,%3}, {%4,%5,%6,%7}, {%8,%9}, {%0,%1,%2,%3};"
                         : "+f"(d[nt][0]), "+f"(d[nt][1]), "+f"(d[nt][2]), "+f"(d[nt][3])
                         : "r"(al0), "r"(al1), "r"(al2), "r"(al3), "r"(bh0), "r"(bh1));
        }
    }

    // epilogue: c0,c1 -> (row0+warpRow+g, nt*8 + tg*2 +{0,1}); c2,c3 -> row+8
    int g = lane >> 2, tg = lane & 3;
    int rlo = row0 + warpRow + g;
    #pragma unroll
    for (int nt = 0; nt < 16; nt++) {
        int col = nt*8 + tg*2;
        *(float2*)(d_hB + (size_t)rlo*128 + col)     = make_float2(d[nt][0], d[nt][1]);
        *(float2*)(d_hB + (size_t)(rlo+8)*128 + col) = make_float2(d[nt][2], d[nt][3]);
    }
}

// ---------------- layer-0 pre ---------------------------------------------------
__global__ void k_pre0(const int* __restrict__ gsrc, const int* __restrict__ gdst) {
    int g = blockIdx.x, t = threadIdx.x;          // 512 threads
    __shared__ int   hist[513];
    __shared__ int   off[512];
    __shared__ float sdinv[512];
    hist[t] = 0;
    if (t == 0) hist[512] = 0;
    __syncthreads();
    int base = g * EPG;
    int ls[8], ld[8];
    #pragma unroll
    for (int q = 0; q < 8; q++) {
        int e = base + t + q*512;
        int s_ = gsrc[e] - g*N0C;
        int d_ = gdst[e] - g*N0C;
        ls[q] = s_; ld[q] = d_;
        d_ls[e] = s_; d_ld[e] = d_; d_w[e] = 1.0f;
        atomicAdd(&hist[d_], 1);
    }
    __syncthreads();
    sdinv[t] = rsqrtf(1.0f + (float)hist[t]);
    d_dinv[g*N0C + t] = sdinv[t];
    __syncthreads();
    if (t == 0) {
        int acc = 0;
        for (int i = 0; i < 512; i++) { int c = hist[i]; hist[i] = acc; acc += c; }
        hist[512] = acc;
    }
    __syncthreads();
    d_rowptr[g*513 + t] = hist[t];
    if (t == 0) d_rowptr[g*513 + 512] = hist[512];
    off[t] = 0;
    __syncthreads();
    #pragma unroll
    for (int q = 0; q < 8; q++) {
        int p = hist[ld[q]] + atomicAdd(&off[ld[q]], 1);
        d_csrc[base + p] = (unsigned short)ls[q];
        d_cen[base + p]  = sdinv[ls[q]] * sdinv[ld[q]];
    }
    if (t < 256) d_reads[g*256 + t] = 0.0f;
    if (g == 0 && t < 128) {
        #pragma unroll
        for (int l = 0; l < 5; l++) { d_bnsum[l][t] = 0.0f; d_bnsq[l][t] = 0.0f; }
    }
}

// --- CSR propagation (warp/dst-node): hC = bias + snorm*self + edges + stats -
__global__ void k_prop(int n, int layer, const float* __restrict__ bias) {
    __shared__ float bsum[128];
    __shared__ float bsq[128];
    __shared__ __align__(16) float sbias[128];
    int t = threadIdx.x;
    if (t < 128) { bsum[t] = 0.0f; bsq[t] = 0.0f; sbias[t] = bias[t]; }
    __syncthreads();

    int wid  = (blockIdx.x*blockDim.x + t) >> 5;
    int lane = t & 31;
    int g  = wid / n;
    int li = wid - g*n;
    int rp0 = d_rowptr[g*513 + li];
    int rp1 = d_rowptr[g*513 + li + 1];
    int base = g * EPG;
    float dv = d_dinv[wid];
    float sn = dv*dv;
    float4 bb = *(float4*)&sbias[lane*4];
    float4 sv = *(const float4*)&d_hB[(size_t)wid*128 + lane*4];
    float4 c = make_float4(bb.x + sn*sv.x, bb.y + sn*sv.y,
                           bb.z + sn*sv.z, bb.w + sn*sv.w);
    for (int idx = rp0; idx < rp1; idx++) {
        float en = d_cen[base + idx];
        int   ls = d_csrc[base + idx];
        float4 v = *(const float4*)&d_hB[(size_t)(g*n + ls)*128 + lane*4];
        c.x += en*v.x; c.y += en*v.y; c.z += en*v.z; c.w += en*v.w;
    }
    *(float4*)&d_hC[(size_t)wid*128 + lane*4] = c;

    atomicAdd(&bsum[lane*4+0], c.x); atomicAdd(&bsq[lane*4+0], c.x*c.x);
    atomicAdd(&bsum[lane*4+1], c.y); atomicAdd(&bsq[lane*4+1], c.y*c.y);
    atomicAdd(&bsum[lane*4+2], c.z); atomicAdd(&bsq[lane*4+2], c.z*c.z);
    atomicAdd(&bsum[lane*4+3], c.w); atomicAdd(&bsq[lane*4+3], c.w*c.w);
    __syncthreads();
    if (t < 128) {
        atomicAdd(&d_bnsum[layer][t], bsum[t]);
        atomicAdd(&d_bnsq[layer][t],  bsq[t]);
    }
}

// ---------------- smem diffusion helper --------------------------------------
__device__ __forceinline__ void pvec_sm(const float* vin, float* vout,
                                        const float* dinv, const int* rp,
                                        const unsigned short* csrc,
                                        const float* cen, int n, int t) {
    for (int i = t; i < n; i += 512) {
        float dv = dinv[i];
        float acc = dv*dv*vin[i];
        int r1 = rp[i+1];
        for (int idx = rp[i]; idx < r1; idx++)
            acc += cen[idx] * vin[csrc[idx]];
        vout[i] = acc;
    }
    __syncthreads();
}

// ---------------- combo: BN apply + scores + Jacobi + topk + pool + remap ---
__global__ void k_combo(int layer, int n, int k, int N,
                        const float* __restrict__ bnW, const float* __restrict__ bnB,
                        const float* __restrict__ attW, const float* __restrict__ theta) {
    int g = blockIdx.x, t = threadIdx.x;      // 512 threads
    __shared__ unsigned short s_csrc[4096];
    __shared__ __align__(16) float s_cen[4096];
    __shared__ int   s_rp[520];
    __shared__ float s_dinv[512];
    __shared__ float s_a[520];
    __shared__ float s_b[512];
    __shared__ float s_c[512];
    __shared__ float s_score[512];
    __shared__ unsigned long long s_key[512];
    __shared__ int   s_newid[512];
    __shared__ __align__(16) float s_scale[128];
    __shared__ __align__(16) float s_shift[128];
    __shared__ __align__(16) float s_att[128];

    int base = g * EPG;
    int ecnt = d_rowptr[g*513 + n];
    if (t < 128) {
        float invN = 1.0f / (float)N;
        float mean = d_bnsum[layer][t] * invN;
        float var  = d_bnsq[layer][t] * invN - mean*mean;
        float sc   = bnW[t] * rsqrtf(var + 1e-5f);
        s_scale[t] = sc;
        s_shift[t] = bnB[t] - mean*sc;
        s_att[t]   = attW[t];
    }
    if (t < n)  s_dinv[t] = d_dinv[g*n + t];
    if (t < n)  s_rp[t] = d_rowptr[g*513 + t];
    if (t == 0) s_rp[n] = ecnt;
    for (int q = t; q < ecnt; q += 512) {
        s_csrc[q] = d_csrc[base + q];
        s_cen[q]  = d_cen[base + q];
    }
    float th0 = theta[0], th1 = theta[1], th2 = theta[2], th3 = theta[3];
    __syncthreads();

    int warp = t >> 5, lane = t & 31;
    for (int row = warp; row < n; row += 16) {
        float4 hv  = *(const float4*)&d_hC[(size_t)(g*n + row)*128 + lane*4];
        float4 scv = *(float4*)&s_scale[lane*4];
        float4 shv = *(float4*)&s_shift[lane*4];
        float4 av  = *(float4*)&s_att[lane*4];
        float p = fmaxf(hv.x*scv.x + shv.x, 0.f)*av.x
                + fmaxf(hv.y*scv.y + shv.y, 0.f)*av.y
                + fmaxf(hv.z*scv.z + shv.z, 0.f)*av.z
                + fmaxf(hv.w*scv.w + shv.w, 0.f)*av.w;
        #pragma unroll
        for (int o = 16; o > 0; o >>= 1) p += __shfl_xor_sync(0xffffffffu, p, o);
        if (lane == 0) { s_a[row] = p; s_score[row] = th0 * p; }
    }
    __syncthreads();

    // Jacobi (A=B=1)
    pvec_sm(s_a, s_c, s_dinv, s_rp, s_csrc, s_cen, n, t);
    for (int i = t; i < n; i += 512) {
        float p1 = 2.0f * s_c[i];
        s_b[i] = p1; s_score[i] += th1 * p1;
    }
    __syncthreads();
    pvec_sm(s_b, s_c, s_dinv, s_rp, s_csrc, s_cen, n, t);
    for (int i = t; i < n; i += 512) {
        float p2 = (120.0f*s_c[i] - 48.0f*s_a[i]) * (1.0f/64.0f);
        s_a[i] = p2; s_score[i] += th2 * p2;
    }
    __syncthreads();
    pvec_sm(s_a, s_c, s_dinv, s_rp, s_csrc, s_cen, n, t);
    for (int i = t; i < n; i += 512) {
        float p3 = (336.0f*s_c[i] - 144.0f*s_b[i]) * (1.0f/180.0f);
        s_score[i] += th3 * p3;
    }
    __syncthreads();

    // bitonic sort desc on packed u64 key (score | ~idx)
    if (t < n)
        s_key[t] = ((unsigned long long)f2u(s_score[t]) << 32)
                 | (unsigned long long)(0xFFFFFFFFu - (unsigned)t);
    for (int size = 2; size <= n; size <<= 1)
        for (int stride = size >> 1; stride > 0; stride >>= 1) {
            __syncthreads();
            if (t < n) {
                int j = t ^ stride;
                if (j > t) {
                    unsigned long long ka = s_key[t], kb = s_key[j];
                    bool aFirst = ka > kb;
                    bool dirB = ((t & size) == 0);
                    if (dirB != aFirst) { s_key[t] = kb; s_key[j] = ka; }
                }
            }
        }
    __syncthreads();
    if (t < n) s_newid[t] = -1;
    __syncthreads();
    if (t < k) s_newid[0xFFFFFFFFu - (unsigned)(s_key[t] & 0xFFFFFFFFull)] = t;
    __syncthreads();

    // pool
    float* pmax = s_cen;
    float* psum = s_cen + 2048;
    float4 vmax = make_float4(-FLT_MAX, -FLT_MAX, -FLT_MAX, -FLT_MAX);
    float4 vsum = make_float4(0.f, 0.f, 0.f, 0.f);
    for (int j = warp; j < k; j += 16) {
        int srcli = 0xFFFFFFFFu - (unsigned)(s_key[j] & 0xFFFFFFFFull);
        float gate = tanhf(s_score[srcli]);
        float4 hv  = *(const float4*)&d_hC[(size_t)(g*n + srcli)*128 + lane*4];
        float4 scv = *(float4*)&s_scale[lane*4];
        float4 shv = *(float4*)&s_shift[lane*4];
        float4 v;
        v.x = fmaxf(hv.x*scv.x + shv.x, 0.f) * gate;
        v.y = fmaxf(hv.y*scv.y + shv.y, 0.f) * gate;
        v.z = fmaxf(hv.z*scv.z + shv.z, 0.f) * gate;
        v.w = fmaxf(hv.w*scv.w + shv.w, 0.f) * gate;
        *(float4*)&d_hA[(size_t)(g*k + j)*128 + lane*4] = v;
        vmax.x = fmaxf(vmax.x, v.x); vmax.y = fmaxf(vmax.y, v.y);
        vmax.z = fmaxf(vmax.z, v.z); vmax.w = fmaxf(vmax.w, v.w);
        vsum.x += v.x; vsum.y += v.y; vsum.z += v.z; vsum.w += v.w;
    }
    *(float4*)&pmax[warp*128 + lane*4] = vmax;
    *(float4*)&psum[warp*128 + lane*4] = vsum;
    __syncthreads();
    if (t < 128) {
        float m = -FLT_MAX, s = 0.f;
        #pragma unroll
        for (int ww = 0; ww < 16; ww++) {
            m = fmaxf(m, pmax[ww*128 + t]);
            s += psum[ww*128 + t];
        }
        d_reads[g*256 + t]       += m;
        d_reads[g*256 + 128 + t] += s / (float)k;
    }

    if (layer == 4) return;

    // remap edges, build next-layer deg/dinv/CSR
    __syncthreads();
    int*   hist  = (int*)s_a;
    int*   offp  = (int*)s_b;
    float* ndinv = s_c;
    if (t < k) hist[t] = 0;
    __syncthreads();
    int eLs[8], eLd[8];
    bool eVal[8];
    #pragma unroll
    for (int q = 0; q < 8; q++) {
        int e = base + t + q*512;
        int ls = d_ls[e], ld = d_ld[e];
        float w = d_w[e];
        int ns = s_newid[ls], nd = s_newid[ld];
        bool val = (ns >= 0) && (nd >= 0) && (w > 0.0f);
        eLs[q] = val ? ns : 0;
        eLd[q] = val ? nd : 0;
        eVal[q] = val;
        d_ls[e] = eLs[q]; d_ld[e] = eLd[q]; d_w[e] = val ? 1.0f : 0.0f;
        if (val) atomicAdd(&hist[nd], 1);
    }
    __syncthreads();
    if (t < k) {
        ndinv[t] = rsqrtf(1.0f + (float)hist[t]);
        d_dinv[g*k + t] = ndinv[t];
    }
    __syncthreads();
    if (t == 0) {
        int acc = 0;
        for (int i = 0; i < k; i++) { int c = hist[i]; hist[i] = acc; acc += c; }
        hist[k] = acc;
    }
    __syncthreads();
    if (t <= k) d_rowptr[g*513 + t] = hist[t];
    if (t < k)  offp[t] = 0;
    __syncthreads();
    #pragma unroll
    for (int q = 0; q < 8; q++) {
        if (eVal[q]) {
            int nd = eLd[q], ns = eLs[q];
            int p = hist[nd] + atomicAdd(&offp[nd], 1);
            d_csrc[base + p] = (unsigned short)ns;
            d_cen[base + p]  = ndinv[ns] * ndinv[nd];
        }
    }
}

// ---------------- MLP head ---------------------------------------------------
__global__ void k_fc1(const float* __restrict__ W, const float* __restrict__ b) {
    int idx = blockIdx.x*blockDim.x + threadIdx.x;   // 16384
    int r = idx >> 7, c = idx & 127;
    float a = b[c];
    for (int j = 0; j < 256; j++) a += d_reads[r*256 + j] * 0.2f * W[j*128 + c];
    d_g1[idx] = a;
}

__global__ void k_fc2(const float* __restrict__ W, const float* __restrict__ b) {
    int idx = blockIdx.x*blockDim.x + threadIdx.x;   // 8192
    int r = idx >> 6, c = idx & 63;
    float a = b[c];
    for (int j = 0; j < 128; j++) a += d_g1[r*128 + j] * W[j*64 + c];
    d_g2[idx] = a;
}

__global__ void k_bnrows(const float* __restrict__ g, const float* __restrict__ b,
                         int rows, int feats, int which) {
    float* data = which ? d_g2 : d_g1;
    int f = threadIdx.x;
    float s = 0.f, q = 0.f;
    for (int r = 0; r < rows; r++) { float v = data[r*feats + f]; s += v; q += v*v; }
    float mean = s / rows;
    float var  = q / rows - mean*mean;
    float sc   = g[f] * rsqrtf(var + 1e-5f);
    float sh   = b[f] - mean*sc;
    for (int r = 0; r < rows; r++) {
        float v = data[r*feats + f]*sc + sh;
        data[r*feats + f] = fmaxf(v, 0.0f);
    }
}

__global__ void k_fc3(const float* __restrict__ W, const float* __restrict__ b,
                      float* __restrict__ out) {
    int r = blockIdx.x, t = threadIdx.x;
    __shared__ float lg[10];
    __shared__ float smx, slse;
    if (t < 10) {
        float a = b[t];
        for (int j = 0; j < 64; j++) a += d_g2[r*64 + j] * W[j*10 + t];
        lg[t] = a;
    }
    __syncthreads();
    if (t == 0) {
        float m = lg[0];
        for (int j = 1; j < 10; j++) m = fmaxf(m, lg[j]);
        float s = 0.f;
        for (int j = 0; j < 10; j++) s += expf(lg[j] - m);
        smx = m; slse = logf(s);
    }
    __syncthreads();
    if (t < 10) out[r*10 + t] = lg[t] - smx - slse;
}

// ---------------- launch -----------------------------------------------------
extern "C" void kernel_launch(void* const* d_in, const int* in_sizes, int n_in,
                              void* d_out, int out_size) {
    const float* x     = (const float*)d_in[0];
    const float* convW = (const float*)d_in[1];
    const float* convb = (const float*)d_in[2];
    const float* bnW   = (const float*)d_in[3];
    const float* bnB   = (const float*)d_in[4];
    const float* bn7W  = (const float*)d_in[5];
    const float* bn7B  = (const float*)d_in[6];
    const float* attW  = (const float*)d_in[7];
    const float* theta = (const float*)d_in[8];
    const float* lin1W = (const float*)d_in[9];
    const float* lin1b = (const float*)d_in[10];
    const float* lin2W = (const float*)d_in[11];
    const float* lin2b = (const float*)d_in[12];
    const float* lin3W = (const float*)d_in[13];
    const float* lin3b = (const float*)d_in[14];
    const int*   src   = (const int*)d_in[15];
    const int*   dst   = (const int*)d_in[16];
    float* out = (float*)d_out;

    float* d_hA_ptr = nullptr;
    cudaGetSymbolAddress((void**)&d_hA_ptr, d_hA);
    cudaFuncSetAttribute(k_gemm_tc, cudaFuncAttributeMaxDynamicSharedMemorySize, SM_TOT);

    k_pre0<<<NB, 512>>>(src, dst);
    k_wprep<<<5, 256>>>(convW);

    int n = N0C;
    for (int i = 0; i < 5; i++) {
        int N = NB * n, k = n / 2;
        const float* in_h = (i == 0) ? x : d_hA_ptr;
        k_gemm_tc<<<N/128, 256, SM_TOT>>>(in_h, i);
        k_prop<<<N/8, 256>>>(n, i, convb + i*H);
        k_combo<<<NB, 512>>>(i, n, k, N, bnW + i*H, bnB + i*H, attW + i*H, theta + i*4);
        n = k;
    }

    k_fc1<<<64, 256>>>(lin1W, lin1b);
    k_bnrows<<<1, 128>>>(bnW + 5*H, bnB + 5*H, 128, 128, 0);
    k_fc2<<<32, 256>>>(lin2W, lin2b);
    k_bnrows<<<1, 64>>>(bn7W, bn7B, 128, 64, 1);
    k_fc3<<<128, 32>>>(lin3W, lin3b, out);
}

// round 14
// speedup vs baseline: 1.1957x; 1.1957x over previous
#include <cuda_runtime.h>
#include <stdint.h>
#include <math.h>
#include <float.h>

#define NB   128
#define N0C  512
#define EPG  4096
#define ETOT (NB*EPG)
#define H    128
#define NMAX (NB*N0C)

// ---------------- scratch ---------------------------------------------------
__device__ float d_hA[NMAX*H];   // layer input h
__device__ float d_hB[NMAX*H];   // m = h @ W
__device__ float d_hC[NMAX*H];   // pre-BN h
__device__ int   d_ls[ETOT];
__device__ int   d_ld[ETOT];
__device__ float d_w[ETOT];
__device__ float2 d_epk[ETOT];   // CSR packed: {enorm, bitcast(src local)}
__device__ int   d_rowptr[NB*513];
__device__ float d_dinv[NMAX];
__device__ float d_bnsum[5][H];
__device__ float d_bnsq[5][H];
__device__ float d_reads[NB*2*H];
__device__ float d_g1[NB*H];
__device__ float d_g2[NB*(H/2)];

// ---------------- f32x2 helpers ---------------------------------------------
__device__ __forceinline__ unsigned long long dup2(float v) {
    unsigned long long r;
    asm("mov.b64 %0, {%1, %1};" : "=l"(r) : "f"(v));
    return r;
}
__device__ __forceinline__ void fma2(unsigned long long& acc,
                                     unsigned long long a, unsigned long long b) {
    asm("fma.rn.f32x2 %0, %1, %2, %3;" : "=l"(acc) : "l"(a), "l"(b), "l"(acc));
}
__device__ __forceinline__ void unpack2(unsigned long long v, float& lo, float& hi) {
    asm("mov.b64 {%0, %1}, %2;" : "=f"(lo), "=f"(hi) : "l"(v));
}
__device__ __forceinline__ unsigned int f2u(float f) {
    unsigned int u = __float_as_uint(f);
    return (u & 0x80000000u) ? ~u : (u | 0x80000000u);
}

// ---------------- layer-0 pre: localize edges, deg/dinv, CSR ----------------
__global__ void k_pre0(const int* __restrict__ gsrc, const int* __restrict__ gdst) {
    int g = blockIdx.x, t = threadIdx.x;          // 512 threads
    __shared__ int   hist[513];
    __shared__ int   off[512];
    __shared__ float sdinv[512];
    hist[t] = 0;
    if (t == 0) hist[512] = 0;
    __syncthreads();
    int base = g * EPG;
    int ls[8], ld[8];
    #pragma unroll
    for (int q = 0; q < 8; q++) {
        int e = base + t + q*512;
        int s_ = gsrc[e] - g*N0C;
        int d_ = gdst[e] - g*N0C;
        ls[q] = s_; ld[q] = d_;
        d_ls[e] = s_; d_ld[e] = d_; d_w[e] = 1.0f;
        atomicAdd(&hist[d_], 1);
    }
    __syncthreads();
    sdinv[t] = rsqrtf(1.0f + (float)hist[t]);
    d_dinv[g*N0C + t] = sdinv[t];
    __syncthreads();
    if (t == 0) {
        int acc = 0;
        for (int i = 0; i < 512; i++) { int c = hist[i]; hist[i] = acc; acc += c; }
        hist[512] = acc;
    }
    __syncthreads();
    d_rowptr[g*513 + t] = hist[t];
    if (t == 0) d_rowptr[g*513 + 512] = hist[512];
    off[t] = 0;
    __syncthreads();
    #pragma unroll
    for (int q = 0; q < 8; q++) {
        int p = hist[ld[q]] + atomicAdd(&off[ld[q]], 1);
        d_epk[base + p] = make_float2(sdinv[ls[q]] * sdinv[ld[q]],
                                      __int_as_float(ls[q]));
    }
    if (t < 256) d_reads[g*256 + t] = 0.0f;
    if (g == 0 && t < 128) {
        #pragma unroll
        for (int l = 0; l < 5; l++) { d_bnsum[l][t] = 0.0f; d_bnsq[l][t] = 0.0f; }
    }
}

// ---------------- GEMM: hB = A@W (fp32x2 packed) -----------------------------
__global__ void k_gemm(const float* __restrict__ A, const float* __restrict__ W) {
    __shared__ __align__(16) float Ast[32][80];
    __shared__ __align__(16) float Bs[32][128];
    int tid  = threadIdx.x;
    int row0 = blockIdx.x * 64;
    int warp = tid >> 5, lane = tid & 31;
    int rBase = warp * 8;
    int cBase = lane * 4;
    unsigned long long acc[4][4];
    #pragma unroll
    for (int rp = 0; rp < 4; rp++)
        #pragma unroll
        for (int c = 0; c < 4; c++) acc[rp][c] = 0ull;

    for (int kt = 0; kt < 4; kt++) {
        int kb = kt * 32;
        #pragma unroll
        for (int l = 0; l < 2; l++) {
            int q = tid + l*256;
            int r = q >> 3, k4 = q & 7;
            float4 a = *(const float4*)(A + (size_t)(row0 + r)*128 + kb + k4*4);
            Ast[k4*4+0][r] = a.x; Ast[k4*4+1][r] = a.y;
            Ast[k4*4+2][r] = a.z; Ast[k4*4+3][r] = a.w;
        }
        #pragma unroll
        for (int l = 0; l < 4; l++) {
            int q = tid + l*256;
            int kk = q >> 5, c4 = q & 31;
            *(float4*)&Bs[kk][c4*4] = *(const float4*)(W + (size_t)(kb + kk)*128 + c4*4);
        }
        __syncthreads();
        #pragma unroll
        for (int kk = 0; kk < 32; kk++) {
            ulonglong2 a01 = *(ulonglong2*)&Ast[kk][rBase];
            ulonglong2 a23 = *(ulonglong2*)&Ast[kk][rBase + 4];
            float4 b = *(float4*)&Bs[kk][cBase];
            unsigned long long b0 = dup2(b.x), b1 = dup2(b.y),
                               b2 = dup2(b.z), b3 = dup2(b.w);
            fma2(acc[0][0], a01.x, b0); fma2(acc[0][1], a01.x, b1);
            fma2(acc[0][2], a01.x, b2); fma2(acc[0][3], a01.x, b3);
            fma2(acc[1][0], a01.y, b0); fma2(acc[1][1], a01.y, b1);
            fma2(acc[1][2], a01.y, b2); fma2(acc[1][3], a01.y, b3);
            fma2(acc[2][0], a23.x, b0); fma2(acc[2][1], a23.x, b1);
            fma2(acc[2][2], a23.x, b2); fma2(acc[2][3], a23.x, b3);
            fma2(acc[3][0], a23.y, b0); fma2(acc[3][1], a23.y, b1);
            fma2(acc[3][2], a23.y, b2); fma2(acc[3][3], a23.y, b3);
        }
        __syncthreads();
    }
    #pragma unroll
    for (int rp = 0; rp < 4; rp++) {
        float lo0, hi0, lo1, hi1, lo2, hi2, lo3, hi3;
        unpack2(acc[rp][0], lo0, hi0); unpack2(acc[rp][1], lo1, hi1);
        unpack2(acc[rp][2], lo2, hi2); unpack2(acc[rp][3], lo3, hi3);
        int rowL = row0 + rBase + 2*rp;
        *(float4*)(d_hB + (size_t)rowL*128 + cBase)     = make_float4(lo0, lo1, lo2, lo3);
        *(float4*)(d_hB + (size_t)(rowL+1)*128 + cBase) = make_float4(hi0, hi1, hi2, hi3);
    }
}

// --- CSR propagation (warp/dst-node): packed meta, x4 unroll, STS stats ------
__global__ void k_prop(int n, int layer, const float* __restrict__ bias) {
    __shared__ float psum[8][128];
    __shared__ float psq[8][128];
    __shared__ __align__(16) float sbias[128];
    int t = threadIdx.x;
    if (t < 128) sbias[t] = bias[t];
    __syncthreads();

    int wid  = (blockIdx.x*blockDim.x + t) >> 5;
    int w    = t >> 5;
    int lane = t & 31;
    int g  = wid / n;
    int li = wid - g*n;
    int rp0 = d_rowptr[g*513 + li];
    int rp1 = d_rowptr[g*513 + li + 1];
    const float2* ep = &d_epk[(size_t)g*EPG];
    const float*  hb = d_hB + (size_t)g*n*128;

    float dv = d_dinv[wid];
    float sn = dv*dv;
    float4 bb = *(float4*)&sbias[lane*4];
    float4 sv = *(const float4*)&d_hB[(size_t)wid*128 + lane*4];
    float4 c = make_float4(bb.x + sn*sv.x, bb.y + sn*sv.y,
                           bb.z + sn*sv.z, bb.w + sn*sv.w);
    float4 a1 = make_float4(0.f,0.f,0.f,0.f);
    float4 a2 = make_float4(0.f,0.f,0.f,0.f);
    float4 a3 = make_float4(0.f,0.f,0.f,0.f);

    int idx = rp0;
    for (; idx + 4 <= rp1; idx += 4) {
        float2 e0 = ep[idx],   e1 = ep[idx+1];
        float2 e2 = ep[idx+2], e3 = ep[idx+3];
        float4 v0 = ((const float4*)(hb + (size_t)__float_as_int(e0.y)*128))[lane];
        float4 v1 = ((const float4*)(hb + (size_t)__float_as_int(e1.y)*128))[lane];
        float4 v2 = ((const float4*)(hb + (size_t)__float_as_int(e2.y)*128))[lane];
        float4 v3 = ((const float4*)(hb + (size_t)__float_as_int(e3.y)*128))[lane];
        c.x  += e0.x*v0.x; c.y  += e0.x*v0.y; c.z  += e0.x*v0.z; c.w  += e0.x*v0.w;
        a1.x += e1.x*v1.x; a1.y += e1.x*v1.y; a1.z += e1.x*v1.z; a1.w += e1.x*v1.w;
        a2.x += e2.x*v2.x; a2.y += e2.x*v2.y; a2.z += e2.x*v2.z; a2.w += e2.x*v2.w;
        a3.x += e3.x*v3.x; a3.y += e3.x*v3.y; a3.z += e3.x*v3.z; a3.w += e3.x*v3.w;
    }
    for (; idx < rp1; idx++) {
        float2 e = ep[idx];
        float4 v = ((const float4*)(hb + (size_t)__float_as_int(e.y)*128))[lane];
        c.x += e.x*v.x; c.y += e.x*v.y; c.z += e.x*v.z; c.w += e.x*v.w;
    }
    c.x += a1.x + a2.x + a3.x;
    c.y += a1.y + a2.y + a3.y;
    c.z += a1.z + a2.z + a3.z;
    c.w += a1.w + a2.w + a3.w;
    *(float4*)&d_hC[(size_t)wid*128 + lane*4] = c;

    // BN stats: conflict-free STS.128 partials, then block reduce
    *(float4*)&psum[w][lane*4] = c;
    *(float4*)&psq[w][lane*4]  = make_float4(c.x*c.x, c.y*c.y, c.z*c.z, c.w*c.w);
    __syncthreads();
    if (t < 128) {
        float s = 0.f, q = 0.f;
        #pragma unroll
        for (int ww = 0; ww < 8; ww++) { s += psum[ww][t]; q += psq[ww][t]; }
        atomicAdd(&d_bnsum[layer][t], s);
        atomicAdd(&d_bnsq[layer][t],  q);
    }
}

// ---------------- smem diffusion helper --------------------------------------
__device__ __forceinline__ void pvec_sm(const float* vin, float* vout,
                                        const float* dinv, const int* rp,
                                        const unsigned short* csrc,
                                        const float* cen, int n, int t) {
    for (int i = t; i < n; i += 512) {
        float dv = dinv[i];
        float acc = dv*dv*vin[i];
        int r1 = rp[i+1];
        for (int idx = rp[i]; idx < r1; idx++)
            acc += cen[idx] * vin[csrc[idx]];
        vout[i] = acc;
    }
    __syncthreads();
}

// ---------------- combo: BN apply + scores + Jacobi + topk + pool + remap ---
__global__ void k_combo(int layer, int n, int k, int N,
                        const float* __restrict__ bnW, const float* __restrict__ bnB,
                        const float* __restrict__ attW, const float* __restrict__ theta) {
    int g = blockIdx.x, t = threadIdx.x;      // 512 threads
    __shared__ unsigned short s_csrc[4096];
    __shared__ __align__(16) float s_cen[4096];   // reused as pool partials
    __shared__ int   s_rp[520];
    __shared__ float s_dinv[512];
    __shared__ float s_a[520];
    __shared__ float s_b[512];
    __shared__ float s_c[512];
    __shared__ float s_score[512];
    __shared__ unsigned long long s_key[512];
    __shared__ int   s_newid[512];
    __shared__ __align__(16) float s_scale[128];
    __shared__ __align__(16) float s_shift[128];
    __shared__ __align__(16) float s_att[128];

    int base = g * EPG;
    int ecnt = d_rowptr[g*513 + n];
    if (t < 128) {
        float invN = 1.0f / (float)N;
        float mean = d_bnsum[layer][t] * invN;
        float var  = d_bnsq[layer][t] * invN - mean*mean;
        float sc   = bnW[t] * rsqrtf(var + 1e-5f);
        s_scale[t] = sc;
        s_shift[t] = bnB[t] - mean*sc;
        s_att[t]   = attW[t];
    }
    if (t < n)  s_dinv[t] = d_dinv[g*n + t];
    if (t < n)  s_rp[t] = d_rowptr[g*513 + t];
    if (t == 0) s_rp[n] = ecnt;
    for (int q = t; q < ecnt; q += 512) {
        float2 e = d_epk[base + q];
        s_csrc[q] = (unsigned short)__float_as_int(e.y);
        s_cen[q]  = e.x;
    }
    float th0 = theta[0], th1 = theta[1], th2 = theta[2], th3 = theta[3];
    __syncthreads();

    int warp = t >> 5, lane = t & 31;
    for (int row = warp; row < n; row += 16) {
        float4 hv  = *(const float4*)&d_hC[(size_t)(g*n + row)*128 + lane*4];
        float4 scv = *(float4*)&s_scale[lane*4];
        float4 shv = *(float4*)&s_shift[lane*4];
        float4 av  = *(float4*)&s_att[lane*4];
        float p = fmaxf(hv.x*scv.x + shv.x, 0.f)*av.x
                + fmaxf(hv.y*scv.y + shv.y, 0.f)*av.y
                + fmaxf(hv.z*scv.z + shv.z, 0.f)*av.z
                + fmaxf(hv.w*scv.w + shv.w, 0.f)*av.w;
        #pragma unroll
        for (int o = 16; o > 0; o >>= 1) p += __shfl_xor_sync(0xffffffffu, p, o);
        if (lane == 0) { s_a[row] = p; s_score[row] = th0 * p; }
    }
    __syncthreads();

    // Jacobi (A=B=1)
    pvec_sm(s_a, s_c, s_dinv, s_rp, s_csrc, s_cen, n, t);
    for (int i = t; i < n; i += 512) {
        float p1 = 2.0f * s_c[i];
        s_b[i] = p1; s_score[i] += th1 * p1;
    }
    __syncthreads();
    pvec_sm(s_b, s_c, s_dinv, s_rp, s_csrc, s_cen, n, t);
    for (int i = t; i < n; i += 512) {
        float p2 = (120.0f*s_c[i] - 48.0f*s_a[i]) * (1.0f/64.0f);
        s_a[i] = p2; s_score[i] += th2 * p2;
    }
    __syncthreads();
    pvec_sm(s_a, s_c, s_dinv, s_rp, s_csrc, s_cen, n, t);
    for (int i = t; i < n; i += 512) {
        float p3 = (336.0f*s_c[i] - 144.0f*s_b[i]) * (1.0f/180.0f);
        s_score[i] += th3 * p3;
    }
    __syncthreads();

    // bitonic sort desc on packed u64 key (score | ~idx)
    if (t < n)
        s_key[t] = ((unsigned long long)f2u(s_score[t]) << 32)
                 | (unsigned long long)(0xFFFFFFFFu - (unsigned)t);
    for (int size = 2; size <= n; size <<= 1)
        for (int stride = size >> 1; stride > 0; stride >>= 1) {
            __syncthreads();
            if (t < n) {
                int j = t ^ stride;
                if (j > t) {
                    unsigned long long ka = s_key[t], kb = s_key[j];
                    bool aFirst = ka > kb;
                    bool dirB = ((t & size) == 0);
                    if (dirB != aFirst) { s_key[t] = kb; s_key[j] = ka; }
                }
            }
        }
    __syncthreads();
    if (t < n) s_newid[t] = -1;
    __syncthreads();
    if (t < k) s_newid[0xFFFFFFFFu - (unsigned)(s_key[t] & 0xFFFFFFFFull)] = t;
    __syncthreads();

    // pool
    float* pmax = s_cen;
    float* psum = s_cen + 2048;
    float4 vmax = make_float4(-FLT_MAX, -FLT_MAX, -FLT_MAX, -FLT_MAX);
    float4 vsum = make_float4(0.f, 0.f, 0.f, 0.f);
    for (int j = warp; j < k; j += 16) {
        int srcli = 0xFFFFFFFFu - (unsigned)(s_key[j] & 0xFFFFFFFFull);
        float gate = tanhf(s_score[srcli]);
        float4 hv  = *(const float4*)&d_hC[(size_t)(g*n + srcli)*128 + lane*4];
        float4 scv = *(float4*)&s_scale[lane*4];
        float4 shv = *(float4*)&s_shift[lane*4];
        float4 v;
        v.x = fmaxf(hv.x*scv.x + shv.x, 0.f) * gate;
        v.y = fmaxf(hv.y*scv.y + shv.y, 0.f) * gate;
        v.z = fmaxf(hv.z*scv.z + shv.z, 0.f) * gate;
        v.w = fmaxf(hv.w*scv.w + shv.w, 0.f) * gate;
        *(float4*)&d_hA[(size_t)(g*k + j)*128 + lane*4] = v;
        vmax.x = fmaxf(vmax.x, v.x); vmax.y = fmaxf(vmax.y, v.y);
        vmax.z = fmaxf(vmax.z, v.z); vmax.w = fmaxf(vmax.w, v.w);
        vsum.x += v.x; vsum.y += v.y; vsum.z += v.z; vsum.w += v.w;
    }
    *(float4*)&pmax[warp*128 + lane*4] = vmax;
    *(float4*)&psum[warp*128 + lane*4] = vsum;
    __syncthreads();
    if (t < 128) {
        float m = -FLT_MAX, s = 0.f;
        #pragma unroll
        for (int ww = 0; ww < 16; ww++) {
            m = fmaxf(m, pmax[ww*128 + t]);
            s += psum[ww*128 + t];
        }
        d_reads[g*256 + t]       += m;
        d_reads[g*256 + 128 + t] += s / (float)k;
    }

    if (layer == 4) return;

    // remap edges, build next-layer deg/dinv/CSR
    __syncthreads();
    int*   hist  = (int*)s_a;
    int*   offp  = (int*)s_b;
    float* ndinv = s_c;
    if (t < k) hist[t] = 0;
    __syncthreads();
    int eLs[8], eLd[8];
    bool eVal[8];
    #pragma unroll
    for (int q = 0; q < 8; q++) {
        int e = base + t + q*512;
        int ls = d_ls[e], ld = d_ld[e];
        float w = d_w[e];
        int ns = s_newid[ls], nd = s_newid[ld];
        bool val = (ns >= 0) && (nd >= 0) && (w > 0.0f);
        eLs[q] = val ? ns : 0;
        eLd[q] = val ? nd : 0;
        eVal[q] = val;
        d_ls[e] = eLs[q]; d_ld[e] = eLd[q]; d_w[e] = val ? 1.0f : 0.0f;
        if (val) atomicAdd(&hist[nd], 1);
    }
    __syncthreads();
    if (t < k) {
        ndinv[t] = rsqrtf(1.0f + (float)hist[t]);
        d_dinv[g*k + t] = ndinv[t];
    }
    __syncthreads();
    if (t == 0) {
        int acc = 0;
        for (int i = 0; i < k; i++) { int c = hist[i]; hist[i] = acc; acc += c; }
        hist[k] = acc;
    }
    __syncthreads();
    if (t <= k) d_rowptr[g*513 + t] = hist[t];
    if (t < k)  offp[t] = 0;
    __syncthreads();
    #pragma unroll
    for (int q = 0; q < 8; q++) {
        if (eVal[q]) {
            int nd = eLd[q], ns = eLs[q];
            int p = hist[nd] + atomicAdd(&offp[nd], 1);
            d_epk[base + p] = make_float2(ndinv[ns] * ndinv[nd],
                                          __int_as_float(ns));
        }
    }
}

// ---------------- MLP head ---------------------------------------------------
__global__ void k_fc1(const float* __restrict__ W, const float* __restrict__ b) {
    int idx = blockIdx.x*blockDim.x + threadIdx.x;   // 16384
    int r = idx >> 7, c = idx & 127;
    float a = b[c];
    for (int j = 0; j < 256; j++) a += d_reads[r*256 + j] * 0.2f * W[j*128 + c];
    d_g1[idx] = a;
}

__global__ void k_fc2(const float* __restrict__ W, const float* __restrict__ b) {
    int idx = blockIdx.x*blockDim.x + threadIdx.x;   // 8192
    int r = idx >> 6, c = idx & 63;
    float a = b[c];
    for (int j = 0; j < 128; j++) a += d_g1[r*128 + j] * W[j*64 + c];
    d_g2[idx] = a;
}

__global__ void k_bnrows(const float* __restrict__ g, const float* __restrict__ b,
                         int rows, int feats, int which) {
    float* data = which ? d_g2 : d_g1;
    int f = threadIdx.x;
    float s = 0.f, q = 0.f;
    for (int r = 0; r < rows; r++) { float v = data[r*feats + f]; s += v; q += v*v; }
    float mean = s / rows;
    float var  = q / rows - mean*mean;
    float sc   = g[f] * rsqrtf(var + 1e-5f);
    float sh   = b[f] - mean*sc;
    for (int r = 0; r < rows; r++) {
        float v = data[r*feats + f]*sc + sh;
        data[r*feats + f] = fmaxf(v, 0.0f);
    }
}

__global__ void k_fc3(const float* __restrict__ W, const float* __restrict__ b,
                      float* __restrict__ out) {
    int r = blockIdx.x, t = threadIdx.x;
    __shared__ float lg[10];
    __shared__ float smx, slse;
    if (t < 10) {
        float a = b[t];
        for (int j = 0; j < 64; j++) a += d_g2[r*64 + j] * W[j*10 + t];
        lg[t] = a;
    }
    __syncthreads();
    if (t == 0) {
        float m = lg[0];
        for (int j = 1; j < 10; j++) m = fmaxf(m, lg[j]);
        float s = 0.f;
        for (int j = 0; j < 10; j++) s += expf(lg[j] - m);
        smx = m; slse = logf(s);
    }
    __syncthreads();
    if (t < 10) out[r*10 + t] = lg[t] - smx - slse;
}

// ---------------- launch -----------------------------------------------------
extern "C" void kernel_launch(void* const* d_in, const int* in_sizes, int n_in,
                              void* d_out, int out_size) {
    const float* x     = (const float*)d_in[0];
    const float* convW = (const float*)d_in[1];
    const float* convb = (const float*)d_in[2];
    const float* bnW   = (const float*)d_in[3];
    const float* bnB   = (const float*)d_in[4];
    const float* bn7W  = (const float*)d_in[5];
    const float* bn7B  = (const float*)d_in[6];
    const float* attW  = (const float*)d_in[7];
    const float* theta = (const float*)d_in[8];
    const float* lin1W = (const float*)d_in[9];
    const float* lin1b = (const float*)d_in[10];
    const float* lin2W = (const float*)d_in[11];
    const float* lin2b = (const float*)d_in[12];
    const float* lin3W = (const float*)d_in[13];
    const float* lin3b = (const float*)d_in[14];
    const int*   src   = (const int*)d_in[15];
    const int*   dst   = (const int*)d_in[16];
    float* out = (float*)d_out;

    float* d_hA_ptr = nullptr;
    cudaGetSymbolAddress((void**)&d_hA_ptr, d_hA);

    k_pre0<<<NB, 512>>>(src, dst);

    int n = N0C;
    for (int i = 0; i < 5; i++) {
        int N = NB * n, k = n / 2;
        const float* in_h = (i == 0) ? x : d_hA_ptr;
        k_gemm<<<N/64, 256>>>(in_h, convW + i*H*H);
        k_prop<<<N/8, 256>>>(n, i, convb + i*H);
        k_combo<<<NB, 512>>>(i, n, k, N, bnW + i*H, bnB + i*H, attW + i*H, theta + i*4);
        n = k;
    }

    k_fc1<<<64, 256>>>(lin1W, lin1b);
    k_bnrows<<<1, 128>>>(bnW + 5*H, bnB + 5*H, 128, 128, 0);
    k_fc2<<<32, 256>>>(lin2W, lin2b);
    k_bnrows<<<1, 64>>>(bn7W, bn7B, 128, 64, 1);
    k_fc3<<<128, 32>>>(lin3W, lin3b, out);
}